// round 2
// baseline (speedup 1.0000x reference)
#include <cuda_runtime.h>
#include <cuda_bf16.h>

// Problem constants
#define BB 8
#define NN 2048
#define DD 128
#define N_LAYER 4
#define N_HEAD 8
#define MAT (DD*DD)            // 16384 floats per 128x128 matrix
#define G0_CHUNKS 16           // split N=2048 into 16 chunks of 128 rows

// ----------------------------- scratch (device globals; no allocation) ----
__device__ __align__(16) float g_part[G0_CHUNKS * BB * MAT]; // 8 MB partial G
__device__ __align__(16) float g_G[2][BB * MAT];
__device__ __align__(16) float g_A[2][BB * MAT];
__device__ __align__(16) float g_T[BB * N_HEAD * MAT];       // 4 MB
__device__ __align__(16) float g_Wp[BB * N_HEAD * MAT];      // 4 MB
__device__ __align__(16) float g_M[BB * MAT];
__device__ __align__(16) float g_P[BB * MAT];

// ----------------------------- core 32x128 GEMM tile (K = 128) ------------
// C[32x128] = op(A)[32x128] @ op(B)[128x128]
// TA: op(A)[m,k] = A[k*lda + m]   else A[m*lda + k]
// TB: op(B)[k,n] = B[n*ldb + k]   else B[k*ldb + n]
template<bool TA, bool TB>
__device__ __forceinline__ void gemm_32x128(const float* __restrict__ A, int lda,
                                            const float* __restrict__ B, int ldb,
                                            float* __restrict__ C)
{
    __shared__ __align__(16) float As[32][33];
    __shared__ __align__(16) float Bs[32][132];

    const int tid = threadIdx.x;       // 256 threads
    const int g   = tid >> 5;          // 0..7  -> rows g*4 .. g*4+3
    const int col = (tid & 31) * 4;    // 0..124

    float acc[4][4];
#pragma unroll
    for (int r = 0; r < 4; r++)
#pragma unroll
        for (int c = 0; c < 4; c++) acc[r][c] = 0.0f;

    for (int k0 = 0; k0 < 128; k0 += 32) {
        // --- load A tile (32x32) ---
#pragma unroll
        for (int t = 0; t < 4; t++) {
            int i = tid + t * 256;
            if (!TA) { int m = i >> 5, k = i & 31; As[m][k] = A[m * lda + k0 + k]; }
            else     { int k = i >> 5, m = i & 31; As[m][k] = A[(k0 + k) * lda + m]; }
        }
        // --- load B tile (32x128) ---
        if (!TB) {
#pragma unroll
            for (int t = 0; t < 4; t++) {
                int v = tid + t * 256;
                int k = v >> 5, n4 = (v & 31) * 4;
                float4 x = *(const float4*)&B[(k0 + k) * ldb + n4];
                Bs[k][n4 + 0] = x.x; Bs[k][n4 + 1] = x.y;
                Bs[k][n4 + 2] = x.z; Bs[k][n4 + 3] = x.w;
            }
        } else {
#pragma unroll
            for (int t = 0; t < 16; t++) {
                int j = tid + t * 256;
                int n = j >> 5, k = j & 31;
                Bs[k][n] = B[n * ldb + k0 + k];
            }
        }
        __syncthreads();

#pragma unroll
        for (int kk = 0; kk < 32; kk++) {
            float4 bv = *(const float4*)&Bs[kk][col];
#pragma unroll
            for (int r = 0; r < 4; r++) {
                float a = As[g * 4 + r][kk];
                acc[r][0] += a * bv.x;
                acc[r][1] += a * bv.y;
                acc[r][2] += a * bv.z;
                acc[r][3] += a * bv.w;
            }
        }
        __syncthreads();
    }

#pragma unroll
    for (int r = 0; r < 4; r++) {
        float4 o = make_float4(acc[r][0], acc[r][1], acc[r][2], acc[r][3]);
        *(float4*)&C[(g * 4 + r) * 128 + col] = o;
    }
}

// ----------------------------- kernels ------------------------------------

// partial G0: for each (chunk, b): part = Zc^T @ Zc, Zc = 128 rows of Z
__global__ __launch_bounds__(256) void k_g0(const float* __restrict__ Z,
                                            float* __restrict__ part)
{
    int chunk = blockIdx.x, b = blockIdx.y, rt = blockIdx.z;
    const float* Zc = Z + (b * NN + chunk * 128) * DD;
    gemm_32x128<true, false>(Zc + rt * 32, DD, Zc, DD,
                             part + (chunk * BB + b) * MAT + rt * 32 * 128);
}

__global__ __launch_bounds__(256) void k_greduce(const float* __restrict__ part,
                                                 float* __restrict__ G)
{
    int e = blockIdx.x * 256 + threadIdx.x;      // 131072 total
    int b = e >> 14, i = e & 16383;
    float s = 0.0f;
#pragma unroll
    for (int c = 0; c < G0_CHUNKS; c++) s += part[(c * BB + b) * MAT + i];
    G[e] = s;
}

__global__ __launch_bounds__(256) void k_initA(float* __restrict__ A)
{
    int e = blockIdx.x * 256 + threadIdx.x;
    int i = e & 16383;
    A[e] = ((i >> 7) == (i & 127)) ? 1.0f : 0.0f;
}

// T[b,j] = Q[l,j] @ G[b]
__global__ __launch_bounds__(256) void k_T(const float* __restrict__ q,
                                           const float* __restrict__ G,
                                           float* __restrict__ T, int l)
{
    int j = blockIdx.x, b = blockIdx.y, rt = blockIdx.z;
    gemm_32x128<false, false>(q + (l * N_HEAD + j) * MAT + rt * 32 * 128, 128,
                              G + b * MAT, 128,
                              T + (b * N_HEAD + j) * MAT + rt * 32 * 128);
}

// Wp[b,j] = T[b,j] @ V[l,j]^T
__global__ __launch_bounds__(256) void k_Wp(const float* __restrict__ T,
                                            const float* __restrict__ v,
                                            float* __restrict__ Wp, int l)
{
    int j = blockIdx.x, b = blockIdx.y, rt = blockIdx.z;
    gemm_32x128<false, true>(T + (b * N_HEAD + j) * MAT + rt * 32 * 128, 128,
                             v + (l * N_HEAD + j) * MAT, 128,
                             Wp + (b * N_HEAD + j) * MAT + rt * 32 * 128);
}

// M[b] = I + (sum_j Wp[b,j]) / (N*N_HEAD)
__global__ __launch_bounds__(256) void k_M(const float* __restrict__ Wp,
                                           float* __restrict__ M)
{
    int e = blockIdx.x * 256 + threadIdx.x;      // 131072 total
    int b = e >> 14, i = e & 16383;
    float s = 0.0f;
#pragma unroll
    for (int j = 0; j < N_HEAD; j++) s += Wp[(b * N_HEAD + j) * MAT + i];
    float id = ((i >> 7) == (i & 127)) ? 1.0f : 0.0f;
    M[e] = id + s * (1.0f / (float(NN) * float(N_HEAD)));
}

// which=0: Anew = A @ M ; which=1: P = G @ M
__global__ __launch_bounds__(256) void k_PA(const float* __restrict__ G,
                                            const float* __restrict__ A,
                                            const float* __restrict__ M,
                                            float* __restrict__ P,
                                            float* __restrict__ Anew)
{
    int which = blockIdx.x, b = blockIdx.y, rt = blockIdx.z;
    const float* src = which ? G : A;
    float*       dst = which ? P : Anew;
    gemm_32x128<false, false>(src + b * MAT + rt * 32 * 128, 128,
                              M + b * MAT, 128,
                              dst + b * MAT + rt * 32 * 128);
}

// Gnext[b] = M[b]^T @ P[b]
__global__ __launch_bounds__(256) void k_Gn(const float* __restrict__ M,
                                            const float* __restrict__ P,
                                            float* __restrict__ Gn)
{
    int b = blockIdx.x, rt = blockIdx.y;
    gemm_32x128<true, false>(M + b * MAT + rt * 32, 128,
                             P + b * MAT, 128,
                             Gn + b * MAT + rt * 32 * 128);
}

// out[b] = Z[b] @ A[b]
__global__ __launch_bounds__(256) void k_out(const float* __restrict__ Z,
                                             const float* __restrict__ A,
                                             float* __restrict__ out)
{
    int tile = blockIdx.x, b = blockIdx.y;   // tile 0..63 (32 rows each)
    const float* Zt = Z + (b * NN + tile * 32) * DD;
    gemm_32x128<false, false>(Zt, DD, A + b * MAT, 128,
                              out + (b * NN + tile * 32) * DD);
}

// ----------------------------- host ---------------------------------------
extern "C" void kernel_launch(void* const* d_in, const int* in_sizes, int n_in,
                              void* d_out, int out_size)
{
    const float* Z = (const float*)d_in[0];        // [8,2048,128]
    const float* v = (const float*)d_in[1];        // [4,8,1,128,128]
    const float* q = (const float*)d_in[2];        // [4,8,1,128,128]
    float* out = (float*)d_out;

    float *pPart, *pG0, *pG1, *pA0, *pA1, *pT, *pWp, *pM, *pP;
    cudaGetSymbolAddress((void**)&pPart, g_part);
    cudaGetSymbolAddress((void**)&pG0, g_G);  pG1 = pG0 + BB * MAT;
    cudaGetSymbolAddress((void**)&pA0, g_A);  pA1 = pA0 + BB * MAT;
    cudaGetSymbolAddress((void**)&pT,  g_T);
    cudaGetSymbolAddress((void**)&pWp, g_Wp);
    cudaGetSymbolAddress((void**)&pM,  g_M);
    cudaGetSymbolAddress((void**)&pP,  g_P);

    // G0 = Z^T Z per batch (chunked + reduce), A = I
    k_g0<<<dim3(G0_CHUNKS, BB, 4), 256>>>(Z, pPart);
    k_greduce<<<512, 256>>>(pPart, pG0);
    k_initA<<<512, 256>>>(pA0);

    float* Gcur = pG0; float* Gnxt = pG1;
    float* Acur = pA0; float* Anxt = pA1;

    for (int l = 0; l < N_LAYER; l++) {
        k_T <<<dim3(N_HEAD, BB, 4), 256>>>(q, Gcur, pT, l);
        k_Wp<<<dim3(N_HEAD, BB, 4), 256>>>(pT, v, pWp, l);
        k_M <<<512, 256>>>(pWp, pM);
        if (l < N_LAYER - 1) {
            k_PA<<<dim3(2, BB, 4), 256>>>(Gcur, Acur, pM, pP, Anxt);
            k_Gn<<<dim3(BB, 4), 256>>>(pM, pP, Gnxt);
        } else {
            k_PA<<<dim3(1, BB, 4), 256>>>(Gcur, Acur, pM, pP, Anxt); // A only
        }
        float* t;
        t = Gcur; Gcur = Gnxt; Gnxt = t;
        t = Acur; Acur = Anxt; Anxt = t;
    }

    k_out<<<dim3(64, BB), 256>>>(Z, Acur, out);
}

// round 3
// speedup vs baseline: 1.0364x; 1.0364x over previous
#include <cuda_runtime.h>

#define BB 8
#define NN 2048
#define DD 128
#define NH 8
#define MAT 16384
#define SCALE (1.0f/16384.0f)   // 1/(N*NH)

#define SA 36     // As[128][36]  (32 used per slab)
#define SB 136    // Bs[32][136]

// ---------------- scratch ----------------
__device__ __align__(16) float g_part[16 * BB * MAT];
__device__ __align__(16) float g_G [BB * MAT];
__device__ __align__(16) float g_R [BB * MAT];
__device__ __align__(16) float g_T [BB * NH * MAT];
__device__ __align__(16) float g_Wp[BB * NH * MAT];
__device__ __align__(16) float g_Wq[BB * MAT];
__device__ __align__(16) float g_U [BB * MAT];

// ---------------- helpers ----------------
__device__ __forceinline__ float tf(float x) {
    float y; asm("cvt.rna.tf32.f32 %0, %1;" : "=f"(y) : "f"(x)); return y;
}
__device__ __forceinline__ float4 tf4(float4 x) {
    x.x = tf(x.x); x.y = tf(x.y); x.z = tf(x.z); x.w = tf(x.w); return x;
}

__device__ __forceinline__ void mma8(float c[4], const float a[4], const float b[2]) {
    asm volatile(
        "mma.sync.aligned.m16n8k8.row.col.f32.tf32.tf32.f32 "
        "{%0,%1,%2,%3}, {%4,%5,%6,%7}, {%8,%9}, {%0,%1,%2,%3};"
        : "+f"(c[0]), "+f"(c[1]), "+f"(c[2]), "+f"(c[3])
        : "r"(__float_as_uint(a[0])), "r"(__float_as_uint(a[1])),
          "r"(__float_as_uint(a[2])), "r"(__float_as_uint(a[3])),
          "r"(__float_as_uint(b[0])), "r"(__float_as_uint(b[1])));
}

// ---------- smem fills (all convert to tf32 via rna) ----------
// As[m][k] = A[m*lda + k0 + k]
__device__ __forceinline__ void fill_A(const float* __restrict__ A, int lda,
                                       int k0, float* __restrict__ As) {
#pragma unroll
    for (int i = 0; i < 4; i++) {
        int idx = threadIdx.x + 256 * i;
        int m = idx >> 3, kf = (idx & 7) * 4;
        *(float4*)(As + m * SA + kf) = tf4(*(const float4*)(A + m * lda + k0 + kf));
    }
}
// As[m][k] = A[(k0+k)*lda + m]   (transposed A)
__device__ __forceinline__ void fill_A_T(const float* __restrict__ A, int lda,
                                         int k0, float* __restrict__ As) {
#pragma unroll
    for (int i = 0; i < 4; i++) {
        int idx = threadIdx.x + 256 * i;
        int k = idx >> 5, mf = (idx & 31) * 4;
        float4 x = tf4(*(const float4*)(A + (k0 + k) * lda + mf));
        As[(mf + 0) * SA + k] = x.x;
        As[(mf + 1) * SA + k] = x.y;
        As[(mf + 2) * SA + k] = x.z;
        As[(mf + 3) * SA + k] = x.w;
    }
}
// Bs[k][n] = B[(k0+k)*ldb + n]
__device__ __forceinline__ void fill_B(const float* __restrict__ B, int ldb,
                                       int k0, float* __restrict__ Bs) {
#pragma unroll
    for (int i = 0; i < 4; i++) {
        int idx = threadIdx.x + 256 * i;
        int k = idx >> 5, nf = (idx & 31) * 4;
        *(float4*)(Bs + k * SB + nf) = tf4(*(const float4*)(B + (k0 + k) * ldb + nf));
    }
}
// Bs[k][n] = B[n*ldb + k0 + k]   (transposed B)
__device__ __forceinline__ void fill_B_T(const float* __restrict__ B, int ldb,
                                         int k0, float* __restrict__ Bs) {
#pragma unroll
    for (int i = 0; i < 4; i++) {
        int idx = threadIdx.x + 256 * i;
        int n = idx >> 3, kf = (idx & 7) * 4;
        float4 x = tf4(*(const float4*)(B + n * ldb + k0 + kf));
        Bs[(kf + 0) * SB + n] = x.x;
        Bs[(kf + 1) * SB + n] = x.y;
        Bs[(kf + 2) * SB + n] = x.z;
        Bs[(kf + 3) * SB + n] = x.w;
    }
}
// Bs[k][n] = B1[(k0+k)*128 + n] + B2[(k0+k)*128 + n]
__device__ __forceinline__ void fill_B2(const float* __restrict__ B1,
                                        const float* __restrict__ B2,
                                        int k0, float* __restrict__ Bs) {
#pragma unroll
    for (int i = 0; i < 4; i++) {
        int idx = threadIdx.x + 256 * i;
        int k = idx >> 5, nf = (idx & 31) * 4;
        float4 x = *(const float4*)(B1 + (k0 + k) * 128 + nf);
        float4 y = *(const float4*)(B2 + (k0 + k) * 128 + nf);
        x.x += y.x; x.y += y.y; x.z += y.z; x.w += y.w;
        *(float4*)(Bs + k * SB + nf) = tf4(x);
    }
}

// ---------- compute one K=32 slab; warp tile 32x64 ----------
__device__ __forceinline__ void compute_slab(const float* __restrict__ As,
                                             const float* __restrict__ Bs,
                                             float acc[2][8][4]) {
    const int lane = threadIdx.x & 31, warp = threadIdx.x >> 5;
    const int mr = (warp & 3) * 32;
    const int nc = (warp >> 2) * 64;
    const int ar = lane >> 2, ac = lane & 3;
    const int bk = lane & 3,  bn = lane >> 2;
#pragma unroll
    for (int k8 = 0; k8 < 32; k8 += 8) {
        float a[2][4];
#pragma unroll
        for (int i = 0; i < 2; i++) {
            const float* ab = As + (mr + 16 * i + ar) * SA + k8 + ac;
            a[i][0] = ab[0];
            a[i][1] = ab[8 * SA];
            a[i][2] = ab[4];
            a[i][3] = ab[8 * SA + 4];
        }
#pragma unroll
        for (int j = 0; j < 8; j++) {
            float b[2];
            const float* bb = Bs + (k8 + bk) * SB + nc + 8 * j + bn;
            b[0] = bb[0];
            b[1] = bb[4 * SB];
            mma8(acc[0][j], a[0], b);
            mma8(acc[1][j], a[1], b);
        }
    }
}

__device__ __forceinline__ void zero_acc(float acc[2][8][4]) {
#pragma unroll
    for (int i = 0; i < 2; i++)
#pragma unroll
        for (int j = 0; j < 8; j++)
#pragma unroll
            for (int r = 0; r < 4; r++) acc[i][j][r] = 0.0f;
}

// store C (128x128, ld=128) with up to two fp32 adds
__device__ __forceinline__ void epilogue(float* __restrict__ C,
                                         const float* __restrict__ add1,
                                         const float* __restrict__ add2,
                                         float acc[2][8][4]) {
    const int lane = threadIdx.x & 31, warp = threadIdx.x >> 5;
    const int r0 = (warp & 3) * 32 + (lane >> 2);
    const int c0 = (warp >> 2) * 64 + 2 * (lane & 3);
#pragma unroll
    for (int i = 0; i < 2; i++)
#pragma unroll
        for (int j = 0; j < 8; j++) {
            int r = r0 + 16 * i, c = c0 + 8 * j;
            float2 lo = make_float2(acc[i][j][0], acc[i][j][1]);
            float2 hi = make_float2(acc[i][j][2], acc[i][j][3]);
            if (add1) {
                float2 x = *(const float2*)(add1 + r * 128 + c);
                float2 y = *(const float2*)(add1 + (r + 8) * 128 + c);
                lo.x += x.x; lo.y += x.y; hi.x += y.x; hi.y += y.y;
            }
            if (add2) {
                float2 x = *(const float2*)(add2 + r * 128 + c);
                float2 y = *(const float2*)(add2 + (r + 8) * 128 + c);
                lo.x += x.x; lo.y += x.y; hi.x += y.x; hi.y += y.y;
            }
            *(float2*)(C + r * 128 + c)       = lo;
            *(float2*)(C + (r + 8) * 128 + c) = hi;
        }
}

#define GEMM_SHARED \
    __shared__ __align__(16) float As[128 * SA]; \
    __shared__ __align__(16) float Bs[32 * SB];  \
    float acc[2][8][4]; zero_acc(acc);

// ---------------- kernels ----------------

// part[chunk,b] = Zc^T @ Zc
__global__ __launch_bounds__(256) void k_g0(const float* __restrict__ Z,
                                            float* __restrict__ part) {
    int chunk = blockIdx.x, b = blockIdx.y;
    const float* Zc = Z + (b * NN + chunk * 128) * DD;
    GEMM_SHARED
    for (int k0 = 0; k0 < 128; k0 += 32) {
        __syncthreads();
        fill_A_T(Zc, DD, k0, As);
        fill_B(Zc, DD, k0, Bs);
        __syncthreads();
        compute_slab(As, Bs, acc);
    }
    epilogue(part + (chunk * BB + b) * MAT, 0, 0, acc);
}

__global__ __launch_bounds__(256) void k_greduce(const float* __restrict__ part,
                                                 float* __restrict__ G) {
    int e = blockIdx.x * 256 + threadIdx.x;   // 131072
    int b = e >> 14, i = e & 16383;
    float s = 0.0f;
#pragma unroll
    for (int c = 0; c < 16; c++) s += part[(c * BB + b) * MAT + i];
    G[e] = s;
}

// T[b,j] = Q[l,j] @ G[b]
__global__ __launch_bounds__(256) void k_T(const float* __restrict__ q,
                                           const float* __restrict__ G,
                                           float* __restrict__ T, int l) {
    int j = blockIdx.x, b = blockIdx.y;
    const float* Ap = q + (l * NH + j) * MAT;
    const float* Bp = G + b * MAT;
    GEMM_SHARED
    for (int k0 = 0; k0 < 128; k0 += 32) {
        __syncthreads();
        fill_A(Ap, 128, k0, As);
        fill_B(Bp, 128, k0, Bs);
        __syncthreads();
        compute_slab(As, Bs, acc);
    }
    epilogue(T + (b * NH + j) * MAT, 0, 0, acc);
}

// Wp[b,j] = T[b,j] @ V[l,j]^T
__global__ __launch_bounds__(256) void k_Wp(const float* __restrict__ T,
                                            const float* __restrict__ v,
                                            float* __restrict__ Wp, int l) {
    int j = blockIdx.x, b = blockIdx.y;
    const float* Ap = T + (b * NH + j) * MAT;
    const float* Bp = v + (l * NH + j) * MAT;
    GEMM_SHARED
    for (int k0 = 0; k0 < 128; k0 += 32) {
        __syncthreads();
        fill_A(Ap, 128, k0, As);
        fill_B_T(Bp, 128, k0, Bs);
        __syncthreads();
        compute_slab(As, Bs, acc);
    }
    epilogue(Wp + (b * NH + j) * MAT, 0, 0, acc);
}

// W'[b] = SCALE * sum_j Wp[b,j]; optionally R = W' (layer 0)
__global__ __launch_bounds__(256) void k_Wsum(const float* __restrict__ Wp,
                                              float* __restrict__ Wq,
                                              float* __restrict__ R, int copyR) {
    int e = blockIdx.x * 256 + threadIdx.x;   // 131072
    int b = e >> 14, i = e & 16383;
    float s = 0.0f;
#pragma unroll
    for (int j = 0; j < NH; j++) s += Wp[(b * NH + j) * MAT + i];
    s *= SCALE;
    Wq[e] = s;
    if (copyR) R[e] = s;
}

// which = blockIdx.x + xoff
//   which 0:  U[b] = G[b] @ W'[b]
//   which 1:  R[b] = R[b] @ W'[b] + R[b] + W'[b]   (in-place, writes after all reads)
__global__ __launch_bounds__(256) void k_RU(const float* __restrict__ G,
                                            float* __restrict__ R,
                                            const float* __restrict__ Wq,
                                            float* __restrict__ U, int xoff) {
    int which = blockIdx.x + xoff, b = blockIdx.y;
    const float* Ap = (which ? R : G) + b * MAT;
    const float* Bp = Wq + b * MAT;
    GEMM_SHARED
    for (int k0 = 0; k0 < 128; k0 += 32) {
        __syncthreads();
        fill_A(Ap, 128, k0, As);
        fill_B(Bp, 128, k0, Bs);
        __syncthreads();
        compute_slab(As, Bs, acc);
    }
    if (which) epilogue(R + b * MAT, R + b * MAT, Wq + b * MAT, acc);
    else       epilogue(U + b * MAT, 0, 0, acc);
}

// G[b] = W'[b]^T @ (G[b]+U[b]) + G[b] + U[b]   (in-place safe)
__global__ __launch_bounds__(256) void k_Gn(const float* __restrict__ Wq,
                                            float* __restrict__ G,
                                            const float* __restrict__ U) {
    int b = blockIdx.x;
    const float* Ap = Wq + b * MAT;
    GEMM_SHARED
    for (int k0 = 0; k0 < 128; k0 += 32) {
        __syncthreads();
        fill_A_T(Ap, 128, k0, As);
        fill_B2(G + b * MAT, U + b * MAT, k0, Bs);
        __syncthreads();
        compute_slab(As, Bs, acc);
    }
    epilogue(G + b * MAT, G + b * MAT, U + b * MAT, acc);
}

// out[tile,b] = Z_tile @ R[b] + Z_tile
__global__ __launch_bounds__(256) void k_out(const float* __restrict__ Z,
                                             const float* __restrict__ R,
                                             float* __restrict__ out) {
    int tile = blockIdx.x, b = blockIdx.y;
    const float* Zt = Z + (b * NN + tile * 128) * DD;
    const float* Bp = R + b * MAT;
    GEMM_SHARED
    for (int k0 = 0; k0 < 128; k0 += 32) {
        __syncthreads();
        fill_A(Zt, DD, k0, As);
        fill_B(Bp, 128, k0, Bs);
        __syncthreads();
        compute_slab(As, Bs, acc);
    }
    epilogue(out + (b * NN + tile * 128) * DD, Zt, 0, acc);
}

// ---------------- host ----------------
extern "C" void kernel_launch(void* const* d_in, const int* in_sizes, int n_in,
                              void* d_out, int out_size) {
    const float* Z = (const float*)d_in[0];
    const float* v = (const float*)d_in[1];
    const float* q = (const float*)d_in[2];
    float* out = (float*)d_out;

    float *pPart, *pG, *pR, *pT, *pWp, *pWq, *pU;
    cudaGetSymbolAddress((void**)&pPart, g_part);
    cudaGetSymbolAddress((void**)&pG,  g_G);
    cudaGetSymbolAddress((void**)&pR,  g_R);
    cudaGetSymbolAddress((void**)&pT,  g_T);
    cudaGetSymbolAddress((void**)&pWp, g_Wp);
    cudaGetSymbolAddress((void**)&pWq, g_Wq);
    cudaGetSymbolAddress((void**)&pU,  g_U);

    k_g0<<<dim3(16, BB), 256>>>(Z, pPart);
    k_greduce<<<512, 256>>>(pPart, pG);

    for (int l = 0; l < 4; l++) {
        k_T  <<<dim3(NH, BB), 256>>>(q, pG, pT, l);
        k_Wp <<<dim3(NH, BB), 256>>>(pT, v, pWp, l);
        k_Wsum<<<512, 256>>>(pWp, pWq, pR, l == 0 ? 1 : 0);
        if (l == 0) {
            // R = W' already written by k_Wsum; only need U = G @ W'
            k_RU<<<dim3(1, BB), 256>>>(pG, pR, pWq, pU, 0);
        } else if (l < 3) {
            k_RU<<<dim3(2, BB), 256>>>(pG, pR, pWq, pU, 0);   // U and R
        } else {
            k_RU<<<dim3(1, BB), 256>>>(pG, pR, pWq, pU, 1);   // R only
        }
        if (l < 3) k_Gn<<<BB, 256>>>(pWq, pG, pU);
    }

    k_out<<<dim3(16, BB), 256>>>(Z, pR, out);
}

// round 4
// speedup vs baseline: 1.3175x; 1.2712x over previous
#include <cuda_runtime.h>

#define BB 8
#define NN 2048
#define NH 8
#define MAT 16384
#define SCALE (1.0f/16384.0f)   // 1/(N*NH)
#define SA 132                  // A smem row stride (floats)
#define SBN 136                 // B smem row stride (floats)

// ---------------- scratch (device globals) ----------------
__device__ __align__(16) float g_part[16 * BB * MAT];
__device__ __align__(16) float g_G[2][BB * MAT];
__device__ __align__(16) float g_R [BB * MAT];
__device__ __align__(16) float g_Wp[BB * NH * MAT];
__device__ __align__(16) float g_Wq[BB * MAT];
__device__ __align__(16) float g_U [BB * MAT];

// ---------------- helpers ----------------
__device__ __forceinline__ float tf(float x) {
    float y; asm("cvt.rna.tf32.f32 %0, %1;" : "=f"(y) : "f"(x)); return y;
}
__device__ __forceinline__ float4 tf4(float4 x) {
    x.x = tf(x.x); x.y = tf(x.y); x.z = tf(x.z); x.w = tf(x.w); return x;
}
__device__ __forceinline__ void mma8(float c[4], const float a[4], const float b[2]) {
    asm volatile(
        "mma.sync.aligned.m16n8k8.row.col.f32.tf32.tf32.f32 "
        "{%0,%1,%2,%3}, {%4,%5,%6,%7}, {%8,%9}, {%0,%1,%2,%3};"
        : "+f"(c[0]), "+f"(c[1]), "+f"(c[2]), "+f"(c[3])
        : "r"(__float_as_uint(a[0])), "r"(__float_as_uint(a[1])),
          "r"(__float_as_uint(a[2])), "r"(__float_as_uint(a[3])),
          "r"(__float_as_uint(b[0])), "r"(__float_as_uint(b[1])));
}

// ---------------- smem fills (512 threads, full K=128 resident) ----------
// As[m][k] = tf(A[m*lda + k]), M rows x 128 cols
template<int M>
__device__ __forceinline__ void fillA(const float* __restrict__ A, int lda,
                                      float* __restrict__ As) {
#pragma unroll
    for (int i = 0; i < M / 16; i++) {
        int idx = threadIdx.x + 512 * i;
        int m = idx >> 5, kf = (idx & 31) * 4;
        *(float4*)(As + m * SA + kf) = tf4(*(const float4*)(A + m * lda + kf));
    }
}
// As[m][k] = tf(A[k*lda + moff + m])  (transposed source)
template<int M>
__device__ __forceinline__ void fillAT(const float* __restrict__ A, int lda,
                                       int moff, float* __restrict__ As) {
#pragma unroll
    for (int i = 0; i < M / 16; i++) {
        int idx = threadIdx.x + 512 * i;
        int k, mf;
        if (M == 128) { k = idx >> 5; mf = (idx & 31) * 4; }
        else          { k = idx >> 4; mf = (idx & 15) * 4; }
        float4 x = tf4(*(const float4*)(A + k * lda + moff + mf));
        As[(mf + 0) * SA + k] = x.x;
        As[(mf + 1) * SA + k] = x.y;
        As[(mf + 2) * SA + k] = x.z;
        As[(mf + 3) * SA + k] = x.w;
    }
}
// Bs[k][n] = tf(B[k*ldb + n]), 128x128
__device__ __forceinline__ void fillB(const float* __restrict__ B, int ldb,
                                      float* __restrict__ Bs) {
#pragma unroll
    for (int i = 0; i < 8; i++) {
        int idx = threadIdx.x + 512 * i;
        int k = idx >> 5, nf = (idx & 31) * 4;
        *(float4*)(Bs + k * SBN + nf) = tf4(*(const float4*)(B + k * ldb + nf));
    }
}
// Bs[k][n] = tf(B1[k*128+n] + B2[k*128+n])
__device__ __forceinline__ void fillB2(const float* __restrict__ B1,
                                       const float* __restrict__ B2,
                                       float* __restrict__ Bs) {
#pragma unroll
    for (int i = 0; i < 8; i++) {
        int idx = threadIdx.x + 512 * i;
        int k = idx >> 5, nf = (idx & 31) * 4;
        float4 x = *(const float4*)(B1 + k * 128 + nf);
        float4 y = *(const float4*)(B2 + k * 128 + nf);
        x.x += y.x; x.y += y.y; x.z += y.z; x.w += y.w;
        *(float4*)(Bs + k * SBN + nf) = tf4(x);
    }
}
// Bs[k][n] = tf(B[n*ldb + k])  (transposed source, 128x128) — for V^T
__device__ __forceinline__ void fillBT(const float* __restrict__ B, int ldb,
                                       float* __restrict__ Bs) {
#pragma unroll
    for (int i = 0; i < 8; i++) {
        int idx = threadIdx.x + 512 * i;
        int n = idx >> 5, kf = (idx & 31) * 4;
        float4 x = tf4(*(const float4*)(B + n * ldb + kf));
        Bs[(kf + 0) * SBN + n] = x.x;
        Bs[(kf + 1) * SBN + n] = x.y;
        Bs[(kf + 2) * SBN + n] = x.z;
        Bs[(kf + 3) * SBN + n] = x.w;
    }
}

// ---------------- compute cores (full K, no internal syncs) --------------
// M=128: 16 warps, warp tile 32x32 (warp&3 -> M, warp>>2 -> N)
__device__ __forceinline__ void compute128(const float* __restrict__ As,
                                           const float* __restrict__ Bs,
                                           float acc[2][4][4]) {
    const int lane = threadIdx.x & 31, warp = threadIdx.x >> 5;
    const int mr = (warp & 3) * 32, nc = (warp >> 2) * 32;
    const int ar = lane >> 2, ac = lane & 3;
    const int bk = lane & 3,  bn = lane >> 2;
#pragma unroll
    for (int kk = 0; kk < 128; kk += 8) {
        float a[2][4];
#pragma unroll
        for (int i = 0; i < 2; i++) {
            const float* p = As + (mr + 16 * i + ar) * SA + kk + ac;
            a[i][0] = p[0]; a[i][1] = p[8 * SA]; a[i][2] = p[4]; a[i][3] = p[8 * SA + 4];
        }
#pragma unroll
        for (int j = 0; j < 4; j++) {
            const float* p = Bs + (kk + bk) * SBN + nc + 8 * j + bn;
            float b[2] = { p[0], p[4 * SBN] };
            mma8(acc[0][j], a[0], b);
            mma8(acc[1][j], a[1], b);
        }
    }
}
// M=64: 16 warps, warp tile 16x32 (warp&3 -> M, warp>>2 -> N)
__device__ __forceinline__ void compute64(const float* __restrict__ As,
                                          const float* __restrict__ Bs,
                                          float acc[4][4]) {
    const int lane = threadIdx.x & 31, warp = threadIdx.x >> 5;
    const int mr = (warp & 3) * 16, nc = (warp >> 2) * 32;
    const int ar = lane >> 2, ac = lane & 3;
    const int bk = lane & 3,  bn = lane >> 2;
#pragma unroll
    for (int kk = 0; kk < 128; kk += 8) {
        float a[4];
        const float* p = As + (mr + ar) * SA + kk + ac;
        a[0] = p[0]; a[1] = p[8 * SA]; a[2] = p[4]; a[3] = p[8 * SA + 4];
#pragma unroll
        for (int j = 0; j < 4; j++) {
            const float* q = Bs + (kk + bk) * SBN + nc + 8 * j + bn;
            float b[2] = { q[0], q[4 * SBN] };
            mma8(acc[j], a, b);
        }
    }
}

// ---------------- epilogues (C/add pointers pre-offset, ld = 128) --------
__device__ __forceinline__ void epi128(float* __restrict__ C,
                                       const float* __restrict__ a1,
                                       float acc[2][4][4]) {
    const int lane = threadIdx.x & 31, warp = threadIdx.x >> 5;
    const int r0 = (warp & 3) * 32 + (lane >> 2);
    const int c0 = (warp >> 2) * 32 + 2 * (lane & 3);
#pragma unroll
    for (int i = 0; i < 2; i++)
#pragma unroll
        for (int j = 0; j < 4; j++) {
            int r = r0 + 16 * i, c = c0 + 8 * j;
            float2 lo = make_float2(acc[i][j][0], acc[i][j][1]);
            float2 hi = make_float2(acc[i][j][2], acc[i][j][3]);
            if (a1) {
                float2 x = *(const float2*)(a1 + r * 128 + c);
                float2 y = *(const float2*)(a1 + (r + 8) * 128 + c);
                lo.x += x.x; lo.y += x.y; hi.x += y.x; hi.y += y.y;
            }
            *(float2*)(C + r * 128 + c)       = lo;
            *(float2*)(C + (r + 8) * 128 + c) = hi;
        }
}
__device__ __forceinline__ void epi64(float* __restrict__ C,
                                      const float* __restrict__ a1,
                                      const float* __restrict__ a2,
                                      float acc[4][4]) {
    const int lane = threadIdx.x & 31, warp = threadIdx.x >> 5;
    const int r0 = (warp & 3) * 16 + (lane >> 2);
    const int c0 = (warp >> 2) * 32 + 2 * (lane & 3);
#pragma unroll
    for (int j = 0; j < 4; j++) {
        int c = c0 + 8 * j;
        float2 lo = make_float2(acc[j][0], acc[j][1]);
        float2 hi = make_float2(acc[j][2], acc[j][3]);
        if (a1) {
            float2 x = *(const float2*)(a1 + r0 * 128 + c);
            float2 y = *(const float2*)(a1 + (r0 + 8) * 128 + c);
            lo.x += x.x; lo.y += x.y; hi.x += y.x; hi.y += y.y;
        }
        if (a2) {
            float2 x = *(const float2*)(a2 + r0 * 128 + c);
            float2 y = *(const float2*)(a2 + (r0 + 8) * 128 + c);
            lo.x += x.x; lo.y += x.y; hi.x += y.x; hi.y += y.y;
        }
        *(float2*)(C + r0 * 128 + c)       = lo;
        *(float2*)(C + (r0 + 8) * 128 + c) = hi;
    }
}
// write 64x128 acc (tf32) into As layout [m][k], for chained GEMM
__device__ __forceinline__ void storeT64(float* __restrict__ As, float acc[4][4]) {
    const int lane = threadIdx.x & 31, warp = threadIdx.x >> 5;
    const int r0 = (warp & 3) * 16 + (lane >> 2);
    const int c0 = (warp >> 2) * 32 + 2 * (lane & 3);
#pragma unroll
    for (int j = 0; j < 4; j++) {
        int c = c0 + 8 * j;
        As[r0 * SA + c]           = tf(acc[j][0]);
        As[r0 * SA + c + 1]       = tf(acc[j][1]);
        As[(r0 + 8) * SA + c]     = tf(acc[j][2]);
        As[(r0 + 8) * SA + c + 1] = tf(acc[j][3]);
    }
}
__device__ __forceinline__ void zero4(float acc[4][4]) {
#pragma unroll
    for (int j = 0; j < 4; j++)
#pragma unroll
        for (int r = 0; r < 4; r++) acc[j][r] = 0.0f;
}

// ---------------- kernels ------------------------------------------------

// G0 partials: part[chunk,b] = Zc^T @ Zc
__global__ __launch_bounds__(512) void k_g0(const float* __restrict__ Z,
                                            float* __restrict__ part) {
    extern __shared__ float sm[];
    float* As = sm; float* Bs = sm + 128 * SA;
    int chunk = blockIdx.x, b = blockIdx.y;
    const float* Zc = Z + (b * NN + chunk * 128) * 128;
    fillAT<128>(Zc, 128, 0, As);
    fillB(Zc, 128, Bs);
    __syncthreads();
    float acc[2][4][4];
#pragma unroll
    for (int i = 0; i < 2; i++) zero4(acc[i]);
    compute128(As, Bs, acc);
    epi128(part + (chunk * BB + b) * MAT, 0, acc);
}

__global__ __launch_bounds__(512) void k_greduce(const float* __restrict__ part,
                                                 float* __restrict__ G) {
    int e = blockIdx.x * 512 + threadIdx.x;   // 131072
    int b = e >> 14, i = e & 16383;
    float s = 0.0f;
#pragma unroll
    for (int c = 0; c < 16; c++) s += part[(c * BB + b) * MAT + i];
    G[e] = s;
}

// fused T=Q@G then W=T@V^T, 64-row half per block. grid (j, b, mh)
__global__ __launch_bounds__(512) void k_TW(const float* __restrict__ q,
                                            const float* __restrict__ v,
                                            const float* __restrict__ G,
                                            float* __restrict__ Wp, int l) {
    extern __shared__ float sm[];
    float* As  = sm;                       // Q half, then T half
    float* BsG = sm + 64 * SA;
    float* BsV = BsG + 128 * SBN;
    int j = blockIdx.x, b = blockIdx.y, mh = blockIdx.z;
    const float* Qp = q + (l * NH + j) * MAT + mh * 64 * 128;
    fillA<64>(Qp, 128, As);
    fillB(G + b * MAT, 128, BsG);
    fillBT(v + (l * NH + j) * MAT, 128, BsV);
    __syncthreads();
    float acc[4][4]; zero4(acc);
    compute64(As, BsG, acc);               // T half
    __syncthreads();                       // all reads of Q done
    storeT64(As, acc);
    __syncthreads();
    zero4(acc);
    compute64(As, BsV, acc);               // W half
    epi64(Wp + (b * NH + j) * MAT + mh * 64 * 128, 0, 0, acc);
}

// W'[b] = SCALE * sum_j Wp[b,j]; optionally R = W' (layer 0)
__global__ __launch_bounds__(512) void k_Wsum(const float* __restrict__ Wp,
                                              float* __restrict__ Wq,
                                              float* __restrict__ R, int copyR) {
    int e = blockIdx.x * 512 + threadIdx.x;   // 131072
    int b = e >> 14, i = e & 16383;
    float s = 0.0f;
#pragma unroll
    for (int j = 0; j < NH; j++) s += Wp[(b * NH + j) * MAT + i];
    s *= SCALE;
    Wq[e] = s;
    if (copyR) R[e] = s;
}

// mode 0: U only; mode 1: U (z=0) and R (z=1); mode 2: R only
// U half = G @ W' ; R half = R @ W' + R + W'  (in-place safe per block)
__global__ __launch_bounds__(512) void k_RU(const float* __restrict__ G,
                                            float* __restrict__ R,
                                            const float* __restrict__ Wq,
                                            float* __restrict__ U, int mode) {
    extern __shared__ float sm[];
    float* As = sm; float* Bs = sm + 64 * SA;
    int mh = blockIdx.x, b = blockIdx.y;
    int which = (mode == 2) ? 1 : blockIdx.z;
    const float* Ap = (which ? R : G) + b * MAT + mh * 64 * 128;
    fillA<64>(Ap, 128, As);
    fillB(Wq + b * MAT, 128, Bs);
    __syncthreads();
    float acc[4][4]; zero4(acc);
    compute64(As, Bs, acc);
    if (which) epi64(R + b * MAT + mh * 64 * 128,
                     R + b * MAT + mh * 64 * 128,
                     Wq + b * MAT + mh * 64 * 128, acc);
    else       epi64(U + b * MAT + mh * 64 * 128, 0, 0, acc);
}

// Gn half: Gnxt = W'^T @ (G+U) + G + U    grid (mh, b)
__global__ __launch_bounds__(512) void k_Gn(const float* __restrict__ Wq,
                                            const float* __restrict__ G,
                                            const float* __restrict__ U,
                                            float* __restrict__ Gn) {
    extern __shared__ float sm[];
    float* As = sm; float* Bs = sm + 64 * SA;
    int mh = blockIdx.x, b = blockIdx.y;
    fillAT<64>(Wq + b * MAT, 128, mh * 64, As);
    fillB2(G + b * MAT, U + b * MAT, Bs);
    __syncthreads();
    float acc[4][4]; zero4(acc);
    compute64(As, Bs, acc);
    epi64(Gn + b * MAT + mh * 64 * 128,
          G  + b * MAT + mh * 64 * 128,
          U  + b * MAT + mh * 64 * 128, acc);
}

// out tile = Z_tile @ R + Z_tile    grid (tile16, b)
__global__ __launch_bounds__(512) void k_out(const float* __restrict__ Z,
                                             const float* __restrict__ R,
                                             float* __restrict__ out) {
    extern __shared__ float sm[];
    float* As = sm; float* Bs = sm + 128 * SA;
    int tile = blockIdx.x, b = blockIdx.y;
    const float* Zt = Z + (b * NN + tile * 128) * 128;
    fillA<128>(Zt, 128, As);
    fillB(R + b * MAT, 128, Bs);
    __syncthreads();
    float acc[2][4][4];
#pragma unroll
    for (int i = 0; i < 2; i++) zero4(acc[i]);
    compute128(As, Bs, acc);
    epi128(out + (b * NN + tile * 128) * 128, Zt, acc);
}

// ---------------- host ----------------------------------------------------
#define SZ_BIG   ((128 * SA + 128 * SBN) * 4)            // k_g0 / k_out
#define SZ_TW    ((64 * SA + 2 * 128 * SBN) * 4)
#define SZ_SMALL ((64 * SA + 128 * SBN) * 4)             // k_RU / k_Gn

extern "C" void kernel_launch(void* const* d_in, const int* in_sizes, int n_in,
                              void* d_out, int out_size) {
    const float* Z = (const float*)d_in[0];
    const float* v = (const float*)d_in[1];
    const float* q = (const float*)d_in[2];
    float* out = (float*)d_out;

    cudaFuncSetAttribute(k_g0,  cudaFuncAttributeMaxDynamicSharedMemorySize, SZ_BIG);
    cudaFuncSetAttribute(k_out, cudaFuncAttributeMaxDynamicSharedMemorySize, SZ_BIG);
    cudaFuncSetAttribute(k_TW,  cudaFuncAttributeMaxDynamicSharedMemorySize, SZ_TW);
    cudaFuncSetAttribute(k_RU,  cudaFuncAttributeMaxDynamicSharedMemorySize, SZ_SMALL);
    cudaFuncSetAttribute(k_Gn,  cudaFuncAttributeMaxDynamicSharedMemorySize, SZ_SMALL);

    float *pPart, *pG, *pR, *pWp, *pWq, *pU;
    cudaGetSymbolAddress((void**)&pPart, g_part);
    cudaGetSymbolAddress((void**)&pG,  g_G);
    cudaGetSymbolAddress((void**)&pR,  g_R);
    cudaGetSymbolAddress((void**)&pWp, g_Wp);
    cudaGetSymbolAddress((void**)&pWq, g_Wq);
    cudaGetSymbolAddress((void**)&pU,  g_U);

    float* Gbuf[2] = { pG, pG + BB * MAT };

    k_g0<<<dim3(16, BB), 512, SZ_BIG>>>(Z, pPart);
    k_greduce<<<256, 512>>>(pPart, Gbuf[0]);

    int cur = 0;
    for (int l = 0; l < 4; l++) {
        k_TW<<<dim3(NH, BB, 2), 512, SZ_TW>>>(q, v, Gbuf[cur], pWp, l);
        k_Wsum<<<256, 512>>>(pWp, pWq, pR, l == 0 ? 1 : 0);
        int mode = (l == 0) ? 0 : (l == 3) ? 2 : 1;
        int zz   = (mode == 1) ? 2 : 1;
        k_RU<<<dim3(2, BB, zz), 512, SZ_SMALL>>>(Gbuf[cur], pR, pWq, pU, mode);
        if (l < 3) {
            k_Gn<<<dim3(2, BB), 512, SZ_SMALL>>>(pWq, Gbuf[cur], pU, Gbuf[cur ^ 1]);
            cur ^= 1;
        }
    }

    k_out<<<dim3(16, BB), 512, SZ_BIG>>>(Z, pR, out);
}